// round 8
// baseline (speedup 1.0000x reference)
#include <cuda_runtime.h>

#define EE 25
#define HH 37
#define NJ 6
#define CSTR 6                  // floats per cell, slots [w0,w3,w1,w4,w2,w5]
#define PEC 27                  // padded cols
#define ROWF (PEC * CSTR)       // 162 floats per padded row
#define PHR 40                  // padded rows + guard row (all-zero reads)
#define NF (PHR * ROWF)         // 6480 floats per buffer
#define NTH 512
#define NBAND 19
#define NVP (NBAND * EE)        // 475 vertical pairs
#define GAMMA 0.9f
#define ADDC 12

// dr = {0,1,1,0,-1,-1} ; dc = {1,0,-1,-1,0,1}  packed (d+1), 2 bits per k
#define DR_PACK 105u
#define DC_PACK 2310u

#define SMEM_WORDS (2 * NF + HH + NJ * HH)
#define SMEM_BYTES (SMEM_WORDS * 4)

__device__ __forceinline__ float2 ld2(const float* p) { return *(const float2*)p; }

__global__ __launch_bounds__(NTH, 4) void vin_kernel(
    const float* __restrict__ goals,   // [B,6,25,25]
    const int*   __restrict__ state,   // [B,3]
    const float* __restrict__ obst,    // [B,25,25]
    const int*   __restrict__ n_iter,  // [1]
    float* __restrict__ out)           // [B,4]
{
    extern __shared__ float sm[];
    unsigned* obsh = (unsigned*)(sm + 2 * NF);   // [37]
    unsigned* gbsh = obsh + HH;                  // [6*37]

    const int b   = blockIdx.x;
    const int tid = threadIdx.x;
    const int lane = tid & 31;

    // zero both buffers (incl. halos & guard rows)
    for (int i = tid; i < 2 * NF; i += NTH) sm[i] = 0.0f;

    // build bitmasks (t<37 -> obstacle row, else goal row per j)
    for (int t = tid; t < HH * (NJ + 1); t += NTH) {
        int r, j;
        if (t < HH) { r = t; j = -1; }
        else        { int tt = t - HH; j = tt / HH; r = tt - j * HH; }
        unsigned bits = 0u;
        #pragma unroll 1
        for (int c = 0; c < EE; ++c) {
            int u = r + (c >> 1) - ADDC;
            if (u >= 0 && u < EE) {
                if (j < 0) {
                    if (obst[(b * EE + u) * EE + c] == 0.0f) bits |= (1u << c);
                } else {
                    if (goals[((b * NJ + j) * EE + u) * EE + c] != 0.0f) bits |= (1u << c);
                }
            }
        }
        if (j < 0) obsh[r] = bits; else gbsh[t - HH] = bits;
    }
    __syncthreads();

    const bool active = (tid < NVP);
    int baseA = 0;
    float AmA = 0.0f, AmB = 0.0f;
    unsigned cgA = 0u, cgB = 0u;
    float2 oA0 = {0,0}, oA1 = {0,0}, oA2 = {0,0};
    float2 oB0 = {0,0}, oB1 = {0,0}, oB2 = {0,0};
    bool fb_l = false, fb_r = false;     // need smem fallback for horiz reads
    bool z_l = false, z_r = false;       // horiz neighbor is halo zero

    if (active) {
        int band = tid / EE;
        int c    = tid - band * EE;
        int rA   = 2 * band;
        int rB   = rA + 1;
        baseA = (rA + 1) * ROWF + (c + 1) * CSTR;
        unsigned obA = (obsh[rA] >> c) & 1u;
        int rBc = (rB < HH) ? rB : (HH - 1);
        unsigned obB = (rB < HH) ? ((obsh[rB] >> c) & 1u) : 0u;
        AmA = obA ? GAMMA : 0.0f;
        AmB = obB ? GAMMA : 0.0f;
        unsigned gA = 0u, gB = 0u;
        #pragma unroll
        for (int j = 0; j < NJ; ++j) {
            gA |= ((gbsh[j * HH + rA ] >> c) & 1u) << j;
            gB |= ((gbsh[j * HH + rBc] >> c) & 1u) << j;
        }
        cgA = obA ? gA : 0u;
        cgB = obB ? gB : 0u;

        oA0 = make_float2((cgA &  1u) ? 1.f : 0.f, (cgA &  8u) ? 1.f : 0.f);
        oA1 = make_float2((cgA &  2u) ? 1.f : 0.f, (cgA & 16u) ? 1.f : 0.f);
        oA2 = make_float2((cgA &  4u) ? 1.f : 0.f, (cgA & 32u) ? 1.f : 0.f);
        oB0 = make_float2((cgB &  1u) ? 1.f : 0.f, (cgB &  8u) ? 1.f : 0.f);
        oB1 = make_float2((cgB &  2u) ? 1.f : 0.f, (cgB & 16u) ? 1.f : 0.f);
        oB2 = make_float2((cgB &  4u) ? 1.f : 0.f, (cgB & 32u) ? 1.f : 0.f);

        // horizontal-neighbor sourcing classification
        z_l  = (c == 0);
        z_r  = (c == EE - 1);
        fb_l = (!z_l) && (lane == 0);    // left cell exists but lives in prev warp
        fb_r = (!z_r) && (lane == 31);   // right cell exists but lives in next warp

        // seed sA = C
        *(float2*)(sm + baseA + 0) = oA0;
        *(float2*)(sm + baseA + 2) = oA1;
        *(float2*)(sm + baseA + 4) = oA2;
        *(float2*)(sm + baseA + ROWF + 0) = oB0;
        *(float2*)(sm + baseA + ROWF + 2) = oB1;
        *(float2*)(sm + baseA + ROWF + 4) = oB2;
    }
    __syncthreads();

    const int iters = n_iter[0];
    int spO = 0;

    for (int s = 0; s < iters; ++s) {
        // all lanes participate in shfls (inactive lanes carry zeros)
        float lAx = __shfl_up_sync(0xFFFFFFFFu, oA0.x, 1);
        float lAy = __shfl_up_sync(0xFFFFFFFFu, oA0.y, 1);
        float lBx = __shfl_up_sync(0xFFFFFFFFu, oB0.x, 1);
        float lBy = __shfl_up_sync(0xFFFFFFFFu, oB0.y, 1);
        float rAx = __shfl_down_sync(0xFFFFFFFFu, oA0.x, 1);
        float rAy = __shfl_down_sync(0xFFFFFFFFu, oA0.y, 1);
        float rBx = __shfl_down_sync(0xFFFFFFFFu, oB0.x, 1);
        float rBy = __shfl_down_sync(0xFFFFFFFFu, oB0.y, 1);

        if (active) {
            const float* SA = sm + spO + baseA;
            const float* SB = SA + ROWF;
            float*       DA = sm + (spO ^ NF) + baseA;

            // vertical / diagonal loads (6 LDS.64)
            float2 a2 = ld2(SA + 160);
            float2 a4 = ld2(SA - 160);
            float2 a5 = ld2(SA - 152);
            float2 b1 = ld2(SB + 164);
            float2 b2 = ld2(SB + 160);
            float2 b5 = ld2(SB - 152);

            // horizontal neighbors: shfl / halo-zero / warp-edge smem fallback
            float2 a3, a0, b3, b0;
            if (z_l)       { a3 = make_float2(0.f, 0.f); b3 = a3; }
            else if (fb_l) { a3 = ld2(SA - 6); b3 = ld2(SB - 6); }
            else           { a3 = make_float2(lAx, lAy); b3 = make_float2(lBx, lBy); }
            if (z_r)       { a0 = make_float2(0.f, 0.f); b0 = a0; }
            else if (fb_r) { a0 = ld2(SA + 6); b0 = ld2(SB + 6); }
            else           { a0 = make_float2(rAx, rAy); b0 = make_float2(rBx, rBy); }

            float mA0 = fmaxf(fmaxf(a0.x, a3.x),  fmaxf(oA1.x, oA2.y));
            float mA1 = fmaxf(fmaxf(oB1.x, a4.x), fmaxf(oA2.x, oA0.x));
            float mA2 = fmaxf(fmaxf(a2.x, a5.x),  fmaxf(oA0.y, oA1.x));
            float mA3 = fmaxf(fmaxf(a3.y, a0.y),  fmaxf(oA1.y, oA2.x));
            float mA4 = fmaxf(fmaxf(a4.y, oB1.y), fmaxf(oA2.y, oA0.y));
            float mA5 = fmaxf(fmaxf(a5.y, a2.y),  fmaxf(oA0.x, oA1.y));

            float mB0 = fmaxf(fmaxf(b0.x, b3.x),  fmaxf(oB1.x, oB2.y));
            float mB1 = fmaxf(fmaxf(b1.x, oA1.x), fmaxf(oB2.x, oB0.x));
            float mB2 = fmaxf(fmaxf(b2.x, b5.x),  fmaxf(oB0.y, oB1.x));
            float mB3 = fmaxf(fmaxf(b3.y, b0.y),  fmaxf(oB1.y, oB2.x));
            float mB4 = fmaxf(fmaxf(oA1.y, b1.y), fmaxf(oB2.y, oB0.y));
            float mB5 = fmaxf(fmaxf(b5.y, b2.y),  fmaxf(oB0.x, oB1.y));

            oA0.x = fmaf(AmA, mA0, (cgA &  1u) ? 1.f : 0.f);
            oA0.y = fmaf(AmA, mA3, (cgA &  8u) ? 1.f : 0.f);
            oA1.x = fmaf(AmA, mA1, (cgA &  2u) ? 1.f : 0.f);
            oA1.y = fmaf(AmA, mA4, (cgA & 16u) ? 1.f : 0.f);
            oA2.x = fmaf(AmA, mA2, (cgA &  4u) ? 1.f : 0.f);
            oA2.y = fmaf(AmA, mA5, (cgA & 32u) ? 1.f : 0.f);
            oB0.x = fmaf(AmB, mB0, (cgB &  1u) ? 1.f : 0.f);
            oB0.y = fmaf(AmB, mB3, (cgB &  8u) ? 1.f : 0.f);
            oB1.x = fmaf(AmB, mB1, (cgB &  2u) ? 1.f : 0.f);
            oB1.y = fmaf(AmB, mB4, (cgB & 16u) ? 1.f : 0.f);
            oB2.x = fmaf(AmB, mB2, (cgB &  4u) ? 1.f : 0.f);
            oB2.y = fmaf(AmB, mB5, (cgB & 32u) ? 1.f : 0.f);

            float* DB = DA + ROWF;
            *(float2*)(DA + 0) = oA0;
            *(float2*)(DA + 2) = oA1;
            *(float2*)(DA + 4) = oA2;
            *(float2*)(DB + 0) = oB0;
            *(float2*)(DB + 2) = oB1;
            *(float2*)(DB + 4) = oB2;
        }
        spO ^= NF;
        __syncthreads();
    }
    // sm + spO holds final s_plus = C + gamma*om*max(...)

    if (tid < 4) {
        int a     = tid;
        int alpha = state[b * 3 + 0];
        int u     = state[b * 3 + 1];
        int v     = state[b * 3 + 2];
        int rot   = (alpha + 1) % 6;
        int uu    = u - (v >> 1) + ADDC;

        int p, ddr = 0, ddc = 0;
        int drr = (int)((DR_PACK >> (2 * rot)) & 3u) - 1;
        int dcc = (int)((DC_PACK >> (2 * rot)) & 3u) - 1;
        if (a == 0)      { p = rot; ddr =  drr; ddc =  dcc; }
        else if (a == 1) { p = rot; ddr = -drr; ddc = -dcc; }
        else if (a == 2) { p = (rot + 1) % 6; }
        else             { p = (rot + 5) % 6; }

        float q = 0.0f;
        if ((obsh[uu] >> v) & 1u) {
            q = sm[spO + (uu + ddr + 1) * ROWF + (v + ddc + 1) * CSTR
                   + 2 * (p % 3) + (p / 3)];
        }
        out[b * 4 + a] = q;
    }
}

extern "C" void kernel_launch(void* const* d_in, const int* in_sizes, int n_in,
                              void* d_out, int out_size) {
    const float* goals  = (const float*)d_in[0];
    const int*   state  = (const int*)  d_in[1];
    const float* obst   = (const float*)d_in[2];
    const int*   n_iter = (const int*)  d_in[3];
    float* out = (float*)d_out;

    cudaFuncSetAttribute(vin_kernel,
                         cudaFuncAttributeMaxDynamicSharedMemorySize, SMEM_BYTES);

    int B = out_size / 4;   // 512
    vin_kernel<<<B, NTH, SMEM_BYTES>>>(goals, state, obst, n_iter, out);
}

// round 11
// speedup vs baseline: 2.9869x; 2.9869x over previous
#include <cuda_runtime.h>

#define EE 25
#define HH 37
#define NJ 6
#define CSTR 6                  // floats per cell, slots [w0,w3,w1,w4,w2,w5]
#define PEC 27                  // padded cols
#define ROWF (PEC * CSTR)       // 162 floats per padded row
#define PHR 40                  // padded rows + guard row (all-zero reads)
#define NF (PHR * ROWF)         // 6480 floats per buffer
#define NTH 480
#define NBAND 19
#define NVP (NBAND * EE)        // 475 vertical pairs
#define GAMMA 0.9f
#define ADDC 12
#define NB 2                    // batches per CTA
#define SBAT (2 * NF)           // per-batch float stride (ping+pong)
#define MROW (HH * (NJ + 1))    // 259 mask rows per batch

// dr = {0,1,1,0,-1,-1} ; dc = {1,0,-1,-1,0,1}  packed (d+1), 2 bits per k
#define DR_PACK 105u
#define DC_PACK 2310u

#define SMEM_FLOATS (NB * SBAT)
#define SMEM_WORDS (SMEM_FLOATS + NB * MROW)
#define SMEM_BYTES (SMEM_WORDS * 4)

__device__ __forceinline__ float2 ld2(const float* p) { return *(const float2*)p; }

__global__ __launch_bounds__(NTH, 2) void vin_kernel(
    const float* __restrict__ goals,   // [B,6,25,25]
    const int*   __restrict__ state,   // [B,3]
    const float* __restrict__ obst,    // [B,25,25]
    const int*   __restrict__ n_iter,  // [1]
    float* __restrict__ out)           // [B,4]
{
    extern __shared__ float sm[];
    unsigned* obsh = (unsigned*)(sm + SMEM_FLOATS);  // [NB][37]
    unsigned* gbsh = obsh + NB * HH;                 // [NB][6*37]

    const int b0  = blockIdx.x * NB;
    const int tid = threadIdx.x;

    // zero all buffers (incl. halos & guard rows)
    for (int i = tid; i < SMEM_FLOATS; i += NTH) sm[i] = 0.0f;

    // build bitmasks for both batches (tt<37 -> obstacle row, else goal row)
    for (int t = tid; t < NB * MROW; t += NTH) {
        int X  = t / MROW;
        int tt = t - X * MROW;
        int bb = b0 + X;
        int r, j;
        if (tt < HH) { r = tt; j = -1; }
        else         { int t2 = tt - HH; j = t2 / HH; r = t2 - j * HH; }
        unsigned bits = 0u;
        #pragma unroll 1
        for (int c = 0; c < EE; ++c) {
            int u = r + (c >> 1) - ADDC;
            if (u >= 0 && u < EE) {
                if (j < 0) {
                    if (obst[(bb * EE + u) * EE + c] == 0.0f) bits |= (1u << c);
                } else {
                    if (goals[((bb * NJ + j) * EE + u) * EE + c] != 0.0f) bits |= (1u << c);
                }
            }
        }
        if (j < 0) obsh[X * HH + r] = bits;
        else       gbsh[X * NJ * HH + (tt - HH)] = bits;
    }
    __syncthreads();

    const bool active = (tid < NVP);
    int baseA = 0;
    float AmA[NB], AmB[NB];
    unsigned cgA[NB], cgB[NB];
    float2 oA0[NB], oA1[NB], oA2[NB], oB0[NB], oB1[NB], oB2[NB];
    #pragma unroll
    for (int X = 0; X < NB; ++X) {
        AmA[X] = AmB[X] = 0.f; cgA[X] = cgB[X] = 0u;
        oA0[X] = oA1[X] = oA2[X] = make_float2(0.f, 0.f);
        oB0[X] = oB1[X] = oB2[X] = make_float2(0.f, 0.f);
    }

    if (active) {
        int band = tid / EE;
        int c    = tid - band * EE;
        int rA   = 2 * band;
        int rB   = rA + 1;
        baseA = (rA + 1) * ROWF + (c + 1) * CSTR;
        int rBc = (rB < HH) ? rB : (HH - 1);

        #pragma unroll
        for (int X = 0; X < NB; ++X) {
            unsigned obA = (obsh[X * HH + rA] >> c) & 1u;
            unsigned obB = (rB < HH) ? ((obsh[X * HH + rB] >> c) & 1u) : 0u;
            AmA[X] = obA ? GAMMA : 0.0f;
            AmB[X] = obB ? GAMMA : 0.0f;
            unsigned gA = 0u, gB = 0u;
            #pragma unroll
            for (int j = 0; j < NJ; ++j) {
                gA |= ((gbsh[X * NJ * HH + j * HH + rA ] >> c) & 1u) << j;
                gB |= ((gbsh[X * NJ * HH + j * HH + rBc] >> c) & 1u) << j;
            }
            cgA[X] = obA ? gA : 0u;
            cgB[X] = obB ? gB : 0u;

            oA0[X] = make_float2((cgA[X] &  1u) ? 1.f : 0.f, (cgA[X] &  8u) ? 1.f : 0.f);
            oA1[X] = make_float2((cgA[X] &  2u) ? 1.f : 0.f, (cgA[X] & 16u) ? 1.f : 0.f);
            oA2[X] = make_float2((cgA[X] &  4u) ? 1.f : 0.f, (cgA[X] & 32u) ? 1.f : 0.f);
            oB0[X] = make_float2((cgB[X] &  1u) ? 1.f : 0.f, (cgB[X] &  8u) ? 1.f : 0.f);
            oB1[X] = make_float2((cgB[X] &  2u) ? 1.f : 0.f, (cgB[X] & 16u) ? 1.f : 0.f);
            oB2[X] = make_float2((cgB[X] &  4u) ? 1.f : 0.f, (cgB[X] & 32u) ? 1.f : 0.f);

            float* s0 = sm + X * SBAT + baseA;
            *(float2*)(s0 + 0) = oA0[X];
            *(float2*)(s0 + 2) = oA1[X];
            *(float2*)(s0 + 4) = oA2[X];
            *(float2*)(s0 + ROWF + 0) = oB0[X];
            *(float2*)(s0 + ROWF + 2) = oB1[X];
            *(float2*)(s0 + ROWF + 4) = oB2[X];
        }
    }
    __syncthreads();

    const int iters = n_iter[0];
    int spO = 0;

    for (int s = 0; s < iters; ++s) {
        if (active) {
            #pragma unroll
            for (int X = 0; X < NB; ++X) {
                const float* SA = sm + X * SBAT + spO + baseA;
                const float* SB = SA + ROWF;
                float*       DA = sm + X * SBAT + (spO ^ NF) + baseA;

                float2 a0 = ld2(SA + 6);
                float2 a2 = ld2(SA + 160);
                float2 a3 = ld2(SA - 6);
                float2 a4 = ld2(SA - 160);
                float2 a5 = ld2(SA - 152);
                float2 b0 = ld2(SB + 6);
                float2 b1 = ld2(SB + 164);
                float2 b2 = ld2(SB + 160);
                float2 b3 = ld2(SB - 6);
                float2 b5 = ld2(SB - 152);

                float mA0 = fmaxf(fmaxf(a0.x, a3.x),  fmaxf(oA1[X].x, oA2[X].y));
                float mA1 = fmaxf(fmaxf(oB1[X].x, a4.x), fmaxf(oA2[X].x, oA0[X].x));
                float mA2 = fmaxf(fmaxf(a2.x, a5.x),  fmaxf(oA0[X].y, oA1[X].x));
                float mA3 = fmaxf(fmaxf(a3.y, a0.y),  fmaxf(oA1[X].y, oA2[X].x));
                float mA4 = fmaxf(fmaxf(a4.y, oB1[X].y), fmaxf(oA2[X].y, oA0[X].y));
                float mA5 = fmaxf(fmaxf(a5.y, a2.y),  fmaxf(oA0[X].x, oA1[X].y));

                float mB0 = fmaxf(fmaxf(b0.x, b3.x),  fmaxf(oB1[X].x, oB2[X].y));
                float mB1 = fmaxf(fmaxf(b1.x, oA1[X].x), fmaxf(oB2[X].x, oB0[X].x));
                float mB2 = fmaxf(fmaxf(b2.x, b5.x),  fmaxf(oB0[X].y, oB1[X].x));
                float mB3 = fmaxf(fmaxf(b3.y, b0.y),  fmaxf(oB1[X].y, oB2[X].x));
                float mB4 = fmaxf(fmaxf(oA1[X].y, b1.y), fmaxf(oB2[X].y, oB0[X].y));
                float mB5 = fmaxf(fmaxf(b5.y, b2.y),  fmaxf(oB0[X].x, oB1[X].y));

                oA0[X].x = fmaf(AmA[X], mA0, (cgA[X] &  1u) ? 1.f : 0.f);
                oA0[X].y = fmaf(AmA[X], mA3, (cgA[X] &  8u) ? 1.f : 0.f);
                oA1[X].x = fmaf(AmA[X], mA1, (cgA[X] &  2u) ? 1.f : 0.f);
                oA1[X].y = fmaf(AmA[X], mA4, (cgA[X] & 16u) ? 1.f : 0.f);
                oA2[X].x = fmaf(AmA[X], mA2, (cgA[X] &  4u) ? 1.f : 0.f);
                oA2[X].y = fmaf(AmA[X], mA5, (cgA[X] & 32u) ? 1.f : 0.f);
                oB0[X].x = fmaf(AmB[X], mB0, (cgB[X] &  1u) ? 1.f : 0.f);
                oB0[X].y = fmaf(AmB[X], mB3, (cgB[X] &  8u) ? 1.f : 0.f);
                oB1[X].x = fmaf(AmB[X], mB1, (cgB[X] &  2u) ? 1.f : 0.f);
                oB1[X].y = fmaf(AmB[X], mB4, (cgB[X] & 16u) ? 1.f : 0.f);
                oB2[X].x = fmaf(AmB[X], mB2, (cgB[X] &  4u) ? 1.f : 0.f);
                oB2[X].y = fmaf(AmB[X], mB5, (cgB[X] & 32u) ? 1.f : 0.f);

                float* DB = DA + ROWF;
                *(float2*)(DA + 0) = oA0[X];
                *(float2*)(DA + 2) = oA1[X];
                *(float2*)(DA + 4) = oA2[X];
                *(float2*)(DB + 0) = oB0[X];
                *(float2*)(DB + 2) = oB1[X];
                *(float2*)(DB + 4) = oB2[X];
            }
        }
        spO ^= NF;
        __syncthreads();
    }
    // sm + X*SBAT + spO holds final s_plus for batch X

    if (tid < 4 * NB) {
        int X     = tid >> 2;
        int a     = tid & 3;
        int bb    = b0 + X;
        int alpha = state[bb * 3 + 0];
        int u     = state[bb * 3 + 1];
        int v     = state[bb * 3 + 2];
        int rot   = (alpha + 1) % 6;
        int uu    = u - (v >> 1) + ADDC;

        int p, ddr = 0, ddc = 0;
        int drr = (int)((DR_PACK >> (2 * rot)) & 3u) - 1;
        int dcc = (int)((DC_PACK >> (2 * rot)) & 3u) - 1;
        if (a == 0)      { p = rot; ddr =  drr; ddc =  dcc; }
        else if (a == 1) { p = rot; ddr = -drr; ddc = -dcc; }
        else if (a == 2) { p = (rot + 1) % 6; }
        else             { p = (rot + 5) % 6; }

        float q = 0.0f;
        if ((obsh[X * HH + uu] >> v) & 1u) {
            q = sm[X * SBAT + spO + (uu + ddr + 1) * ROWF + (v + ddc + 1) * CSTR
                   + 2 * (p % 3) + (p / 3)];
        }
        out[bb * 4 + a] = q;
    }
}

extern "C" void kernel_launch(void* const* d_in, const int* in_sizes, int n_in,
                              void* d_out, int out_size) {
    const float* goals  = (const float*)d_in[0];
    const int*   state  = (const int*)  d_in[1];
    const float* obst   = (const float*)d_in[2];
    const int*   n_iter = (const int*)  d_in[3];
    float* out = (float*)d_out;

    cudaFuncSetAttribute(vin_kernel,
                         cudaFuncAttributeMaxDynamicSharedMemorySize, SMEM_BYTES);

    int B = out_size / 4;        // 512
    vin_kernel<<<B / NB, NTH, SMEM_BYTES>>>(goals, state, obst, n_iter, out);
}